// round 1
// baseline (speedup 1.0000x reference)
#include <cuda_runtime.h>
#include <math.h>

#define BB  65536
#define DIN 128
#define HH  256
#define DE  64
#define KC  4096

// ---------------- scratch (static device globals; no allocation) ----------------
__device__ float g_h1[(size_t)BB * HH];   // 64 MB
__device__ float g_h2[(size_t)BB * HH];   // 64 MB
__device__ float g_z [(size_t)BB * DE];   // 16 MB
__device__ float g_ps[256 * HH];
__device__ float g_pq[256 * HH];
__device__ float g_scale[HH];
__device__ float g_shift[HH];
__device__ float g_c2[KC];
__device__ int   g_idx[BB];

// ---------------- tiled fp32 GEMM: C[M,N] = op(A)[M,K] @ B[K,N] + bias -----------
// EPI: 0 = bias only, 1 = bias+ReLU, 2 = bias+tanh
// BNPRO: apply h -> max(h*scale[k]+shift[k], 0) to A elements on load (BN+ReLU)
template<int EPI, bool BNPRO>
__global__ void __launch_bounds__(256) sgemm_kernel(
    const float* __restrict__ A, const float* __restrict__ Bm,
    const float* __restrict__ bias, float* __restrict__ C,
    int M, int N, int K)
{
    __shared__ float As[8][128];
    __shared__ float Bs[8][132];

    const int tid = threadIdx.x;
    const int tx = tid & 15, ty = tid >> 4;
    const int m0 = blockIdx.y * 128, n0 = blockIdx.x * 128;
    const int ar = tid >> 1,  ac = (tid & 1) * 4;   // A tile: 128 rows x 8 k
    const int br = tid >> 5,  bc = (tid & 31) * 4;  // B tile: 8 rows x 128 n

    float acc[8][8];
    #pragma unroll
    for (int i = 0; i < 8; i++)
        #pragma unroll
        for (int j = 0; j < 8; j++) acc[i][j] = 0.f;

    for (int k0 = 0; k0 < K; k0 += 8) {
        float4 av = *reinterpret_cast<const float4*>(A + (size_t)(m0 + ar) * K + (k0 + ac));
        if (BNPRO) {
            av.x = fmaxf(fmaf(av.x, g_scale[k0 + ac + 0], g_shift[k0 + ac + 0]), 0.f);
            av.y = fmaxf(fmaf(av.y, g_scale[k0 + ac + 1], g_shift[k0 + ac + 1]), 0.f);
            av.z = fmaxf(fmaf(av.z, g_scale[k0 + ac + 2], g_shift[k0 + ac + 2]), 0.f);
            av.w = fmaxf(fmaf(av.w, g_scale[k0 + ac + 3], g_shift[k0 + ac + 3]), 0.f);
        }
        As[ac + 0][ar] = av.x;
        As[ac + 1][ar] = av.y;
        As[ac + 2][ar] = av.z;
        As[ac + 3][ar] = av.w;

        float4 bv = make_float4(0.f, 0.f, 0.f, 0.f);
        if (n0 + bc < N)
            bv = *reinterpret_cast<const float4*>(Bm + (size_t)(k0 + br) * N + (n0 + bc));
        *reinterpret_cast<float4*>(&Bs[br][bc]) = bv;

        __syncthreads();
        #pragma unroll
        for (int kk = 0; kk < 8; kk++) {
            float a[8], b[8];
            *reinterpret_cast<float4*>(&a[0]) = *reinterpret_cast<const float4*>(&As[kk][ty * 8 + 0]);
            *reinterpret_cast<float4*>(&a[4]) = *reinterpret_cast<const float4*>(&As[kk][ty * 8 + 4]);
            *reinterpret_cast<float4*>(&b[0]) = *reinterpret_cast<const float4*>(&Bs[kk][tx * 8 + 0]);
            *reinterpret_cast<float4*>(&b[4]) = *reinterpret_cast<const float4*>(&Bs[kk][tx * 8 + 4]);
            #pragma unroll
            for (int i = 0; i < 8; i++)
                #pragma unroll
                for (int j = 0; j < 8; j++)
                    acc[i][j] = fmaf(a[i], b[j], acc[i][j]);
        }
        __syncthreads();
    }

    #pragma unroll
    for (int i = 0; i < 8; i++) {
        const int m = m0 + ty * 8 + i;
        #pragma unroll
        for (int j = 0; j < 8; j++) {
            const int n = n0 + tx * 8 + j;
            if (n < N) {
                float v = acc[i][j] + bias[n];
                if (EPI == 1) v = fmaxf(v, 0.f);
                if (EPI == 2) v = tanhf(v);
                C[(size_t)m * N + n] = v;
            }
        }
    }
}

// ---------------- BatchNorm statistics (deterministic two-stage) -----------------
__global__ void __launch_bounds__(256) bn_partial_kernel(const float* __restrict__ h)
{
    const int j = threadIdx.x;      // feature column
    const int b = blockIdx.x;       // 256-row chunk
    const float* p = h + (size_t)b * 256 * HH + j;
    float s = 0.f, q = 0.f;
    #pragma unroll 8
    for (int r = 0; r < 256; r++) {
        float v = p[(size_t)r * HH];
        s += v;
        q = fmaf(v, v, q);
    }
    g_ps[b * HH + j] = s;
    g_pq[b * HH + j] = q;
}

__global__ void bn_finalize_kernel(const float* __restrict__ gamma,
                                   const float* __restrict__ beta)
{
    const int j = threadIdx.x;
    float s = 0.f, q = 0.f;
    for (int b = 0; b < 256; b++) { s += g_ps[b * HH + j]; q += g_pq[b * HH + j]; }
    const float mean = s * (1.f / (float)BB);
    const float var  = q * (1.f / (float)BB) - mean * mean;   // biased variance
    const float inv  = rsqrtf(var + 1e-5f);
    const float sc   = gamma[j] * inv;
    g_scale[j] = sc;
    g_shift[j] = beta[j] - mean * sc;
}

// ---------------- codebook squared norms -----------------------------------------
__global__ void c2_kernel(const float* __restrict__ cb)
{
    const int k = blockIdx.x * 256 + threadIdx.x;
    if (k < KC) {
        float s = 0.f;
        #pragma unroll
        for (int j = 0; j < DE; j++) {
            float v = cb[(size_t)k * DE + j];
            s = fmaf(v, v, s);
        }
        g_c2[k] = s;
    }
}

// ---------------- fused distance + argmin -----------------------------------------
// Per block: 64 z-rows. Loop over 64 chunks of 64 codes.
// Threads: 256 = 16(ty: 4 rows each) x 16(tx: 4 codes each, interleaved c*16+tx).
__global__ void __launch_bounds__(256) dist_argmin_kernel(
    const float* __restrict__ z, const float* __restrict__ cb,
    int* __restrict__ idxo)
{
    __shared__ float zs[64 * 65];
    __shared__ float cs[64 * 65];
    __shared__ float c2s[64];
    __shared__ float rs[64 * 16];
    __shared__ int   ri[64 * 16];

    const int tid = threadIdx.x;
    const int tx = tid & 15, ty = tid >> 4;
    const int row0 = blockIdx.x * 64;

    // stage z tile [64 x 64]
    #pragma unroll
    for (int t = 0; t < 16; t++) {
        int lin = t * 256 + tid;
        int r = lin >> 6, c = lin & 63;
        zs[r * 65 + c] = z[(size_t)(row0 + r) * DE + c];
    }

    float best[4];
    int   bi[4];
    #pragma unroll
    for (int i = 0; i < 4; i++) { best[i] = 3.4e38f; bi[i] = 0x7fffffff; }

    for (int ch = 0; ch < 64; ch++) {
        __syncthreads();
        #pragma unroll
        for (int t = 0; t < 16; t++) {
            int lin = t * 256 + tid;
            int r = lin >> 6, c = lin & 63;
            cs[r * 65 + c] = cb[(size_t)(ch * 64 + r) * DE + c];
        }
        if (tid < 64) c2s[tid] = g_c2[ch * 64 + tid];
        __syncthreads();

        float dot[4][4];
        #pragma unroll
        for (int i = 0; i < 4; i++)
            #pragma unroll
            for (int c = 0; c < 4; c++) dot[i][c] = 0.f;

        #pragma unroll 8
        for (int kk = 0; kk < 64; kk++) {
            float zv[4], cv[4];
            #pragma unroll
            for (int i = 0; i < 4; i++) zv[i] = zs[(ty * 4 + i) * 65 + kk];
            #pragma unroll
            for (int c = 0; c < 4; c++) cv[c] = cs[(c * 16 + tx) * 65 + kk];
            #pragma unroll
            for (int i = 0; i < 4; i++)
                #pragma unroll
                for (int c = 0; c < 4; c++)
                    dot[i][c] = fmaf(zv[i], cv[c], dot[i][c]);
        }

        #pragma unroll
        for (int c = 0; c < 4; c++) {
            const int gi = ch * 64 + c * 16 + tx;     // increases monotonically per thread
            const float cc = c2s[c * 16 + tx];
            #pragma unroll
            for (int i = 0; i < 4; i++) {
                float s = fmaf(-2.f, dot[i][c], cc);  // ||e||^2 - 2 z.e (||z||^2 const per row)
                if (s < best[i]) { best[i] = s; bi[i] = gi; }
            }
        }
    }

    __syncthreads();
    #pragma unroll
    for (int i = 0; i < 4; i++) {
        rs[(ty * 4 + i) * 16 + tx] = best[i];
        ri[(ty * 4 + i) * 16 + tx] = bi[i];
    }
    __syncthreads();

    if (tid < 64) {
        float bs = 3.4e38f;
        int   b  = 0x7fffffff;
        for (int t = 0; t < 16; t++) {
            float s = rs[tid * 16 + t];
            int  id = ri[tid * 16 + t];
            if (s < bs || (s == bs && id < b)) { bs = s; b = id; }
        }
        idxo[row0 + tid] = b;
    }
}

// ---------------- output writer ----------------------------------------------------
// mode 0: out = [idx as float (B)] ++ [z_q (B*64)]  (float32)
// mode 1: out = z_q only (float32)
// mode 2: out = idx only (int32)
__global__ void writeout_kernel(const float* __restrict__ cb,
                                float* __restrict__ outf, int* __restrict__ outi,
                                int mode)
{
    const int gid = blockIdx.x * 256 + threadIdx.x;   // over B*64
    const int row = gid >> 6, j = gid & 63;
    const int id = g_idx[row];
    if (mode == 0) {
        if (j == 0) outf[row] = (float)id;
        outf[BB + gid] = cb[(size_t)id * DE + j];
    } else if (mode == 1) {
        outf[gid] = cb[(size_t)id * DE + j];
    } else {
        if (j == 0) outi[row] = id;
    }
}

// ---------------- launch -----------------------------------------------------------
extern "C" void kernel_launch(void* const* d_in, const int* in_sizes, int n_in,
                              void* d_out, int out_size)
{
    const float* x     = (const float*)d_in[0];
    const float* W1    = (const float*)d_in[1];
    const float* b1    = (const float*)d_in[2];
    const float* gamma = (const float*)d_in[3];
    const float* beta  = (const float*)d_in[4];
    const float* W2    = (const float*)d_in[5];
    const float* b2    = (const float*)d_in[6];
    const float* W3    = (const float*)d_in[7];
    const float* b3    = (const float*)d_in[8];
    const float* cb    = (const float*)d_in[9];

    float *h1p = nullptr, *h2p = nullptr, *zp = nullptr;
    int *idxp = nullptr;
    cudaGetSymbolAddress((void**)&h1p, g_h1);
    cudaGetSymbolAddress((void**)&h2p, g_h2);
    cudaGetSymbolAddress((void**)&zp,  g_z);
    cudaGetSymbolAddress((void**)&idxp, g_idx);

    dim3 blk(256);

    // h1 = x @ W1 + b1
    sgemm_kernel<0, false><<<dim3(HH / 128, BB / 128), blk>>>(x, W1, b1, h1p, BB, HH, DIN);

    // BN stats (deterministic)
    bn_partial_kernel<<<256, 256>>>(h1p);
    bn_finalize_kernel<<<1, HH>>>(gamma, beta);

    // h2 = relu( bnrelu(h1) @ W2 + b2 )
    sgemm_kernel<1, true><<<dim3(HH / 128, BB / 128), blk>>>(h1p, W2, b2, h2p, BB, HH, HH);

    // z = tanh( h2 @ W3 + b3 )
    sgemm_kernel<2, false><<<dim3(1, BB / 128), blk>>>(h2p, W3, b3, zp, BB, DE, HH);

    // codebook norms + fused argmin
    c2_kernel<<<KC / 256, 256>>>(cb);
    dist_argmin_kernel<<<BB / 64, 256>>>(zp, cb, idxp);

    // outputs
    int mode;
    if      (out_size == BB * (DE + 1)) mode = 0;
    else if (out_size == BB * DE)       mode = 1;
    else                                mode = 2;
    writeout_kernel<<<(BB * DE) / 256, 256>>>(cb, (float*)d_out, (int*)d_out, mode);
}

// round 3
// speedup vs baseline: 1.2109x; 1.2109x over previous
#include <cuda_runtime.h>
#include <math.h>
#include <stdint.h>

#define BB  65536
#define DIN 128
#define HH  256
#define DE  64
#define KC  4096

// ---------------- scratch (static device globals; no allocation) ----------------
__device__ float g_h1[(size_t)BB * HH];
__device__ float g_h2[(size_t)BB * HH];
__device__ float g_z [(size_t)BB * DE];
__device__ float g_ps[256 * HH];
__device__ float g_pq[256 * HH];
__device__ float g_scale[HH];
__device__ float g_shift[HH];
__device__ float g_c2[KC];
__device__ int   g_idx[BB];

// ---------------- tiled fp32 GEMM (unchanged, known-good) -----------------
template<int EPI, bool BNPRO>
__global__ void __launch_bounds__(256) sgemm_kernel(
    const float* __restrict__ A, const float* __restrict__ Bm,
    const float* __restrict__ bias, float* __restrict__ C,
    int M, int N, int K)
{
    __shared__ float As[8][128];
    __shared__ float Bs[8][132];

    const int tid = threadIdx.x;
    const int tx = tid & 15, ty = tid >> 4;
    const int m0 = blockIdx.y * 128, n0 = blockIdx.x * 128;
    const int ar = tid >> 1,  ac = (tid & 1) * 4;
    const int br = tid >> 5,  bc = (tid & 31) * 4;

    float acc[8][8];
    #pragma unroll
    for (int i = 0; i < 8; i++)
        #pragma unroll
        for (int j = 0; j < 8; j++) acc[i][j] = 0.f;

    for (int k0 = 0; k0 < K; k0 += 8) {
        float4 av = *reinterpret_cast<const float4*>(A + (size_t)(m0 + ar) * K + (k0 + ac));
        if (BNPRO) {
            av.x = fmaxf(fmaf(av.x, g_scale[k0 + ac + 0], g_shift[k0 + ac + 0]), 0.f);
            av.y = fmaxf(fmaf(av.y, g_scale[k0 + ac + 1], g_shift[k0 + ac + 1]), 0.f);
            av.z = fmaxf(fmaf(av.z, g_scale[k0 + ac + 2], g_shift[k0 + ac + 2]), 0.f);
            av.w = fmaxf(fmaf(av.w, g_scale[k0 + ac + 3], g_shift[k0 + ac + 3]), 0.f);
        }
        As[ac + 0][ar] = av.x;
        As[ac + 1][ar] = av.y;
        As[ac + 2][ar] = av.z;
        As[ac + 3][ar] = av.w;

        float4 bv = make_float4(0.f, 0.f, 0.f, 0.f);
        if (n0 + bc < N)
            bv = *reinterpret_cast<const float4*>(Bm + (size_t)(k0 + br) * N + (n0 + bc));
        *reinterpret_cast<float4*>(&Bs[br][bc]) = bv;

        __syncthreads();
        #pragma unroll
        for (int kk = 0; kk < 8; kk++) {
            float a[8], b[8];
            *reinterpret_cast<float4*>(&a[0]) = *reinterpret_cast<const float4*>(&As[kk][ty * 8 + 0]);
            *reinterpret_cast<float4*>(&a[4]) = *reinterpret_cast<const float4*>(&As[kk][ty * 8 + 4]);
            *reinterpret_cast<float4*>(&b[0]) = *reinterpret_cast<const float4*>(&Bs[kk][tx * 8 + 0]);
            *reinterpret_cast<float4*>(&b[4]) = *reinterpret_cast<const float4*>(&Bs[kk][tx * 8 + 4]);
            #pragma unroll
            for (int i = 0; i < 8; i++)
                #pragma unroll
                for (int j = 0; j < 8; j++)
                    acc[i][j] = fmaf(a[i], b[j], acc[i][j]);
        }
        __syncthreads();
    }

    #pragma unroll
    for (int i = 0; i < 8; i++) {
        const int m = m0 + ty * 8 + i;
        #pragma unroll
        for (int j = 0; j < 8; j++) {
            const int n = n0 + tx * 8 + j;
            if (n < N) {
                float v = acc[i][j] + bias[n];
                if (EPI == 1) v = fmaxf(v, 0.f);
                if (EPI == 2) v = tanhf(v);
                C[(size_t)m * N + n] = v;
            }
        }
    }
}

// ---------------- BatchNorm statistics (unchanged) -----------------
__global__ void __launch_bounds__(256) bn_partial_kernel(const float* __restrict__ h)
{
    const int j = threadIdx.x;
    const int b = blockIdx.x;
    const float* p = h + (size_t)b * 256 * HH + j;
    float s = 0.f, q = 0.f;
    #pragma unroll 8
    for (int r = 0; r < 256; r++) {
        float v = p[(size_t)r * HH];
        s += v;
        q = fmaf(v, v, q);
    }
    g_ps[b * HH + j] = s;
    g_pq[b * HH + j] = q;
}

__global__ void bn_finalize_kernel(const float* __restrict__ gamma,
                                   const float* __restrict__ beta)
{
    const int j = threadIdx.x;
    float s = 0.f, q = 0.f;
    for (int b = 0; b < 256; b++) { s += g_ps[b * HH + j]; q += g_pq[b * HH + j]; }
    const float mean = s * (1.f / (float)BB);
    const float var  = q * (1.f / (float)BB) - mean * mean;
    const float inv  = rsqrtf(var + 1e-5f);
    const float sc   = gamma[j] * inv;
    g_scale[j] = sc;
    g_shift[j] = beta[j] - mean * sc;
}

// ---------------- codebook squared norms (unchanged) -----------------
__global__ void c2_kernel(const float* __restrict__ cb)
{
    const int k = blockIdx.x * 256 + threadIdx.x;
    if (k < KC) {
        float s = 0.f;
        #pragma unroll
        for (int j = 0; j < DE; j++) {
            float v = cb[(size_t)k * DE + j];
            s = fmaf(v, v, s);
        }
        g_c2[k] = s;
    }
}

// ================= mma.sync tf32 3x-split dist + argmin =================
// CTA: 256 threads = 8 warps as 2 (row) x 4 (col) panels.
// CTA tile: 128 z-rows x 128 codes per chunk, 32 chunks, K=64 (8 k-steps).
// Warp tile: 64 rows x 32 codes = 4x4 m16n8k8 tiles.
// Z and CB chunks staged in smem in FRAGMENT ORDER (conflict-free LDS.128/64).

__device__ __forceinline__ uint32_t f2tf32(float v) {
    uint32_t r;
    asm("cvt.rna.tf32.f32 %0, %1;" : "=r"(r) : "f"(v));
    return r;
}
__device__ __forceinline__ void mma_tf32(float c[4], uint32_t a0, uint32_t a1,
                                         uint32_t a2, uint32_t a3,
                                         uint32_t b0, uint32_t b1) {
    asm volatile(
        "mma.sync.aligned.m16n8k8.row.col.f32.tf32.tf32.f32 "
        "{%0,%1,%2,%3}, {%4,%5,%6,%7}, {%8,%9}, {%0,%1,%2,%3};"
        : "+f"(c[0]), "+f"(c[1]), "+f"(c[2]), "+f"(c[3])
        : "r"(a0), "r"(a1), "r"(a2), "r"(a3), "r"(b0), "r"(b1));
}

// smem layout (bytes)
#define D_A_HI 0          // 8 mtiles x 8 ksteps x 32 lanes x 4 u32 = 32KB
#define D_A_LO 32768
#define D_B_HI 65536      // 16 ntiles x 8 ksteps x 32 lanes x 2 u32 = 32KB
#define D_B_LO 98304
#define D_C2   131072     // 128 floats
#define D_REDF 131584     // 128 x 16 floats = 8KB
#define D_REDI 139776     // 128 x 16 ints   = 8KB
#define D_SMEM 147968

__global__ void __launch_bounds__(256, 1) dist_argmin_mma(
    const float* __restrict__ z, const float* __restrict__ cb, int* __restrict__ idxo)
{
    extern __shared__ char smem[];
    uint32_t* sAhi = (uint32_t*)(smem + D_A_HI);
    uint32_t* sAlo = (uint32_t*)(smem + D_A_LO);
    uint32_t* sBhi = (uint32_t*)(smem + D_B_HI);
    uint32_t* sBlo = (uint32_t*)(smem + D_B_LO);
    float*    c2s  = (float*)(smem + D_C2);
    float*    redF = (float*)(smem + D_REDF);
    int*      redI = (int*)(smem + D_REDI);

    const int tid  = threadIdx.x;
    const int lane = tid & 31;
    const int wid  = tid >> 5;
    const int wr   = wid >> 2;      // 0..1 row panel
    const int wc   = wid & 3;       // 0..3 col panel
    const int row0 = blockIdx.x * 128;

    // ---- stage Z tile [128 x 64] into fragment-order hi/lo ----
    #pragma unroll
    for (int t = 0; t < 32; t++) {
        const int lin = t * 256 + tid;
        const int r = lin >> 6, k = lin & 63;
        const float v = z[(size_t)(row0 + r) * DE + k];
        const uint32_t hi = f2tf32(v);
        const uint32_t lo = f2tf32(v - __uint_as_float(hi));
        const int mt = r >> 4, rr = r & 15;
        const int ks = k >> 3, kk = k & 7;
        const int fl = (rr & 7) * 4 + (kk & 3);
        const int rg = (rr >> 3) + 2 * (kk >> 2);
        const int o  = ((mt * 8 + ks) * 32 + fl) * 4 + rg;
        sAhi[o] = hi;
        sAlo[o] = lo;
    }

    float bestv[8];
    int   besti[8];
    #pragma unroll
    for (int s = 0; s < 8; s++) { bestv[s] = 3.4e38f; besti[s] = 0; }

    for (int ch = 0; ch < 32; ch++) {
        __syncthreads();   // previous epilogue's c2s reads done
        // ---- stage CB chunk [128 codes x 64] fragment-order hi/lo ----
        const float* src = cb + (size_t)ch * 128 * 64;
        #pragma unroll
        for (int t = 0; t < 32; t++) {
            const int lin = t * 256 + tid;
            const int n = lin >> 6, k = lin & 63;
            const float v = src[lin];
            const uint32_t hi = f2tf32(v);
            const uint32_t lo = f2tf32(v - __uint_as_float(hi));
            const int nt = n >> 3, nn = n & 7;
            const int ks = k >> 3, kk = k & 7;
            const int o  = ((nt * 8 + ks) * 32 + nn * 4 + (kk & 3)) * 2 + (kk >> 2);
            sBhi[o] = hi;
            sBlo[o] = lo;
        }
        if (tid < 128) c2s[tid] = g_c2[ch * 128 + tid];
        __syncthreads();

        // ---- mma mainloop ----
        float acc[4][4][4];
        #pragma unroll
        for (int mt = 0; mt < 4; mt++)
            #pragma unroll
            for (int nt = 0; nt < 4; nt++)
                #pragma unroll
                for (int j = 0; j < 4; j++) acc[mt][nt][j] = 0.f;

        #pragma unroll
        for (int ks = 0; ks < 8; ks++) {
            uint4 ahi[4], alo[4];
            uint2 bhi[4], blo[4];
            #pragma unroll
            for (int mt = 0; mt < 4; mt++) {
                const int o = (((wr * 4 + mt) * 8 + ks) * 32 + lane) * 4;
                ahi[mt] = *reinterpret_cast<const uint4*>(sAhi + o);
                alo[mt] = *reinterpret_cast<const uint4*>(sAlo + o);
            }
            #pragma unroll
            for (int nt = 0; nt < 4; nt++) {
                const int o = (((wc * 4 + nt) * 8 + ks) * 32 + lane) * 2;
                bhi[nt] = *reinterpret_cast<const uint2*>(sBhi + o);
                blo[nt] = *reinterpret_cast<const uint2*>(sBlo + o);
            }
            #pragma unroll
            for (int mt = 0; mt < 4; mt++)
                #pragma unroll
                for (int nt = 0; nt < 4; nt++)
                    mma_tf32(acc[mt][nt], ahi[mt].x, ahi[mt].y, ahi[mt].z, ahi[mt].w,
                             bhi[nt].x, bhi[nt].y);
            #pragma unroll
            for (int mt = 0; mt < 4; mt++)
                #pragma unroll
                for (int nt = 0; nt < 4; nt++)
                    mma_tf32(acc[mt][nt], ahi[mt].x, ahi[mt].y, ahi[mt].z, ahi[mt].w,
                             blo[nt].x, blo[nt].y);
            #pragma unroll
            for (int mt = 0; mt < 4; mt++)
                #pragma unroll
                for (int nt = 0; nt < 4; nt++)
                    mma_tf32(acc[mt][nt], alo[mt].x, alo[mt].y, alo[mt].z, alo[mt].w,
                             bhi[nt].x, bhi[nt].y);
        }

        // ---- epilogue: dist = c2 - 2*dot, track per-slot argmin ----
        // C frag: c0 (row g, col 2q), c1 (row g, col 2q+1), c2 (row g+8, ...), c3
        // slot s = mt*2 + half; iteration order keeps gi strictly increasing -> '<'
        #pragma unroll
        for (int nt = 0; nt < 4; nt++) {
            const int ncol = wc * 32 + nt * 8 + 2 * (lane & 3);
            const float cc0 = c2s[ncol];
            const float cc1 = c2s[ncol + 1];
            const int gi = ch * 128 + ncol;
            #pragma unroll
            for (int mt = 0; mt < 4; mt++) {
                float d0 = fmaf(-2.f, acc[mt][nt][0], cc0);
                float d1 = fmaf(-2.f, acc[mt][nt][1], cc1);
                float d2 = fmaf(-2.f, acc[mt][nt][2], cc0);
                float d3 = fmaf(-2.f, acc[mt][nt][3], cc1);
                const int s0 = mt * 2, s1 = mt * 2 + 1;
                if (d0 < bestv[s0]) { bestv[s0] = d0; besti[s0] = gi; }
                if (d1 < bestv[s0]) { bestv[s0] = d1; besti[s0] = gi + 1; }
                if (d2 < bestv[s1]) { bestv[s1] = d2; besti[s1] = gi; }
                if (d3 < bestv[s1]) { bestv[s1] = d3; besti[s1] = gi + 1; }
            }
        }
    }

    __syncthreads();
    // ---- cross-thread reduction: 16 candidates per row ----
    #pragma unroll
    for (int s = 0; s < 8; s++) {
        const int mt = s >> 1, half = s & 1;
        const int row = wr * 64 + mt * 16 + half * 8 + (lane >> 2);
        const int e = wc * 4 + (lane & 3);
        redF[row * 16 + e] = bestv[s];
        redI[row * 16 + e] = besti[s];
    }
    __syncthreads();
    if (tid < 128) {
        float bs = 3.4e38f;
        int   b  = 0x7fffffff;
        #pragma unroll
        for (int e = 0; e < 16; e++) {
            const float sv = redF[tid * 16 + e];
            const int   iv = redI[tid * 16 + e];
            if (sv < bs || (sv == bs && iv < b)) { bs = sv; b = iv; }
        }
        idxo[row0 + tid] = b;
    }
}

// ---------------- output writer (unchanged) ----------------
__global__ void writeout_kernel(const float* __restrict__ cb,
                                float* __restrict__ outf, int* __restrict__ outi,
                                int mode)
{
    const int gid = blockIdx.x * 256 + threadIdx.x;
    const int row = gid >> 6, j = gid & 63;
    const int id = g_idx[row];
    if (mode == 0) {
        if (j == 0) outf[row] = (float)id;
        outf[BB + gid] = cb[(size_t)id * DE + j];
    } else if (mode == 1) {
        outf[gid] = cb[(size_t)id * DE + j];
    } else {
        if (j == 0) outi[row] = id;
    }
}

// ---------------- launch -----------------------------------------------------------
extern "C" void kernel_launch(void* const* d_in, const int* in_sizes, int n_in,
                              void* d_out, int out_size)
{
    const float* x     = (const float*)d_in[0];
    const float* W1    = (const float*)d_in[1];
    const float* b1    = (const float*)d_in[2];
    const float* gamma = (const float*)d_in[3];
    const float* beta  = (const float*)d_in[4];
    const float* W2    = (const float*)d_in[5];
    const float* b2    = (const float*)d_in[6];
    const float* W3    = (const float*)d_in[7];
    const float* b3    = (const float*)d_in[8];
    const float* cb    = (const float*)d_in[9];

    float *h1p = nullptr, *h2p = nullptr, *zp = nullptr;
    int *idxp = nullptr;
    cudaGetSymbolAddress((void**)&h1p, g_h1);
    cudaGetSymbolAddress((void**)&h2p, g_h2);
    cudaGetSymbolAddress((void**)&zp,  g_z);
    cudaGetSymbolAddress((void**)&idxp, g_idx);

    cudaFuncSetAttribute(dist_argmin_mma, cudaFuncAttributeMaxDynamicSharedMemorySize, D_SMEM);

    dim3 blk(256);

    // h1 = x @ W1 + b1
    sgemm_kernel<0, false><<<dim3(HH / 128, BB / 128), blk>>>(x, W1, b1, h1p, BB, HH, DIN);

    // BN stats (deterministic)
    bn_partial_kernel<<<256, 256>>>(h1p);
    bn_finalize_kernel<<<1, HH>>>(gamma, beta);

    // h2 = relu( bnrelu(h1) @ W2 + b2 )
    sgemm_kernel<1, true><<<dim3(HH / 128, BB / 128), blk>>>(h1p, W2, b2, h2p, BB, HH, HH);

    // z = tanh( h2 @ W3 + b3 )
    sgemm_kernel<2, false><<<dim3(1, BB / 128), blk>>>(h2p, W3, b3, zp, BB, DE, HH);

    // codebook norms + tensor-core dist/argmin
    c2_kernel<<<KC / 256, 256>>>(cb);
    dist_argmin_mma<<<BB / 128, 256, D_SMEM>>>(zp, cb, idxp);

    // outputs
    int mode;
    if      (out_size == BB * (DE + 1)) mode = 0;
    else if (out_size == BB * DE)       mode = 1;
    else                                mode = 2;
    writeout_kernel<<<(BB * DE) / 256, 256>>>(cb, (float*)d_out, (int*)d_out, mode);
}

// round 4
// speedup vs baseline: 1.3467x; 1.1122x over previous
#include <cuda_runtime.h>
#include <math.h>
#include <stdint.h>

#define BB  65536
#define DIN 128
#define HH  256
#define DE  64
#define KC  4096

// ---------------- scratch (static device globals; no allocation) ----------------
__device__ float g_h1[(size_t)BB * HH];
__device__ float g_h2[(size_t)BB * HH];
__device__ float g_z [(size_t)BB * DE];
__device__ float g_ps[512 * HH];
__device__ float g_pq[512 * HH];
__device__ float g_scale[HH];
__device__ float g_shift[HH];
__device__ float g_c2[KC];
__device__ int   g_idx[BB];
__device__ uint32_t g_cbhi[32 * 8192];   // codebook tf32-hi, fragment order, per chunk
__device__ uint32_t g_cblo[32 * 8192];   // codebook tf32-lo

__device__ __forceinline__ uint32_t f2tf32(float v) {
    uint32_t r;
    asm("cvt.rna.tf32.f32 %0, %1;" : "=r"(r) : "f"(v));
    return r;
}

// ================= double-buffered fp32 GEMM, 128x128 tile =================
// EPI: 0 = bias, 1 = bias+ReLU. BNPRO: A-prologue h->max(h*sc+sh,0). BNACC: BN partial sums.
template<int EPI, bool BNPRO, bool BNACC>
__global__ void __launch_bounds__(256, 2) sgemm128_kernel(
    const float* __restrict__ A, const float* __restrict__ Bm,
    const float* __restrict__ bias, float* __restrict__ C,
    float* __restrict__ ps, float* __restrict__ pq,
    int M, int N, int K)
{
    __shared__ float As[2][8][128];
    __shared__ float Bs[2][8][132];
    __shared__ float red[BNACC ? 2 * 16 * 128 : 1];
    __shared__ float ssc[BNPRO ? 256 : 1];
    __shared__ float ssh[BNPRO ? 256 : 1];

    const int tid = threadIdx.x;
    const int tx = tid & 15, ty = tid >> 4;
    const int m0 = blockIdx.y * 128, n0 = blockIdx.x * 128;
    const int ar = tid >> 1, ac = (tid & 1) * 4;
    const int br = tid >> 5, bc = (tid & 31) * 4;

    if (BNPRO) {
        ssc[tid] = g_scale[tid];
        ssh[tid] = g_shift[tid];
        __syncthreads();
    }

    // prologue: tile k0 = 0
    {
        float4 av = *reinterpret_cast<const float4*>(A + (size_t)(m0 + ar) * K + ac);
        if (BNPRO) {
            av.x = fmaxf(fmaf(av.x, ssc[ac + 0], ssh[ac + 0]), 0.f);
            av.y = fmaxf(fmaf(av.y, ssc[ac + 1], ssh[ac + 1]), 0.f);
            av.z = fmaxf(fmaf(av.z, ssc[ac + 2], ssh[ac + 2]), 0.f);
            av.w = fmaxf(fmaf(av.w, ssc[ac + 3], ssh[ac + 3]), 0.f);
        }
        float4 bv = *reinterpret_cast<const float4*>(Bm + (size_t)br * N + n0 + bc);
        As[0][ac + 0][ar] = av.x;
        As[0][ac + 1][ar] = av.y;
        As[0][ac + 2][ar] = av.z;
        As[0][ac + 3][ar] = av.w;
        *reinterpret_cast<float4*>(&Bs[0][br][bc]) = bv;
    }
    __syncthreads();

    float acc[8][8] = {};
    int buf = 0;

    for (int k0 = 8; k0 <= K; k0 += 8) {
        const bool has = (k0 < K);
        float4 av_n, bv_n;
        if (has) {
            av_n = *reinterpret_cast<const float4*>(A + (size_t)(m0 + ar) * K + (k0 + ac));
            if (BNPRO) {
                av_n.x = fmaxf(fmaf(av_n.x, ssc[k0 + ac + 0], ssh[k0 + ac + 0]), 0.f);
                av_n.y = fmaxf(fmaf(av_n.y, ssc[k0 + ac + 1], ssh[k0 + ac + 1]), 0.f);
                av_n.z = fmaxf(fmaf(av_n.z, ssc[k0 + ac + 2], ssh[k0 + ac + 2]), 0.f);
                av_n.w = fmaxf(fmaf(av_n.w, ssc[k0 + ac + 3], ssh[k0 + ac + 3]), 0.f);
            }
            bv_n = *reinterpret_cast<const float4*>(Bm + (size_t)(k0 + br) * N + (n0 + bc));
        }
        #pragma unroll
        for (int kk = 0; kk < 8; kk++) {
            float a[8], b[8];
            *reinterpret_cast<float4*>(&a[0]) = *reinterpret_cast<const float4*>(&As[buf][kk][ty * 8 + 0]);
            *reinterpret_cast<float4*>(&a[4]) = *reinterpret_cast<const float4*>(&As[buf][kk][ty * 8 + 4]);
            *reinterpret_cast<float4*>(&b[0]) = *reinterpret_cast<const float4*>(&Bs[buf][kk][tx * 8 + 0]);
            *reinterpret_cast<float4*>(&b[4]) = *reinterpret_cast<const float4*>(&Bs[buf][kk][tx * 8 + 4]);
            #pragma unroll
            for (int i = 0; i < 8; i++)
                #pragma unroll
                for (int j = 0; j < 8; j++)
                    acc[i][j] = fmaf(a[i], b[j], acc[i][j]);
        }
        if (has) {
            As[buf ^ 1][ac + 0][ar] = av_n.x;
            As[buf ^ 1][ac + 1][ar] = av_n.y;
            As[buf ^ 1][ac + 2][ar] = av_n.z;
            As[buf ^ 1][ac + 3][ar] = av_n.w;
            *reinterpret_cast<float4*>(&Bs[buf ^ 1][br][bc]) = bv_n;
            __syncthreads();
            buf ^= 1;
        }
    }

    // epilogue
    float cs[8], cq[8];
    #pragma unroll
    for (int j = 0; j < 8; j++) { cs[j] = 0.f; cq[j] = 0.f; }

    #pragma unroll
    for (int i = 0; i < 8; i++) {
        const int m = m0 + ty * 8 + i;
        #pragma unroll
        for (int j = 0; j < 8; j++) {
            const int n = n0 + tx * 8 + j;
            float v = acc[i][j] + bias[n];
            if (EPI == 1) v = fmaxf(v, 0.f);
            C[(size_t)m * N + n] = v;
            if (BNACC) { cs[j] += v; cq[j] = fmaf(v, v, cq[j]); }
        }
    }

    if (BNACC) {
        #pragma unroll
        for (int j = 0; j < 8; j++) {
            red[ty * 128 + tx * 8 + j]        = cs[j];
            red[2048 + ty * 128 + tx * 8 + j] = cq[j];
        }
        __syncthreads();
        if (tid < 128) {
            float s = 0.f, q = 0.f;
            #pragma unroll
            for (int t = 0; t < 16; t++) {
                s += red[t * 128 + tid];
                q += red[2048 + t * 128 + tid];
            }
            ps[(size_t)blockIdx.y * HH + n0 + tid] = s;
            pq[(size_t)blockIdx.y * HH + n0 + tid] = q;
        }
    }
}

// ================= GEMM3: 128x64 tile, tanh epilogue, double-buffered =================
__global__ void __launch_bounds__(256, 2) sgemm_z_kernel(
    const float* __restrict__ A, const float* __restrict__ Bm,
    const float* __restrict__ bias, float* __restrict__ C, int K)
{
    __shared__ float As[2][8][128];
    __shared__ float Bs[2][8][68];

    const int tid = threadIdx.x;
    const int tx = tid & 7, ty = tid >> 3;     // 8 col-groups x 32 row-groups
    const int m0 = blockIdx.x * 128;
    const int ar = tid >> 1, ac = (tid & 1) * 4;
    const int br = tid >> 5, bc = (tid & 31) * 2;

    {
        float4 av = *reinterpret_cast<const float4*>(A + (size_t)(m0 + ar) * K + ac);
        float2 bv = *reinterpret_cast<const float2*>(Bm + (size_t)br * DE + bc);
        As[0][ac + 0][ar] = av.x;
        As[0][ac + 1][ar] = av.y;
        As[0][ac + 2][ar] = av.z;
        As[0][ac + 3][ar] = av.w;
        *reinterpret_cast<float2*>(&Bs[0][br][bc]) = bv;
    }
    __syncthreads();

    float acc[4][8] = {};
    int buf = 0;

    for (int k0 = 8; k0 <= K; k0 += 8) {
        const bool has = (k0 < K);
        float4 av_n;
        float2 bv_n;
        if (has) {
            av_n = *reinterpret_cast<const float4*>(A + (size_t)(m0 + ar) * K + (k0 + ac));
            bv_n = *reinterpret_cast<const float2*>(Bm + (size_t)(k0 + br) * DE + bc);
        }
        #pragma unroll
        for (int kk = 0; kk < 8; kk++) {
            float a[4], b[8];
            *reinterpret_cast<float4*>(&a[0]) = *reinterpret_cast<const float4*>(&As[buf][kk][ty * 4]);
            *reinterpret_cast<float4*>(&b[0]) = *reinterpret_cast<const float4*>(&Bs[buf][kk][tx * 8 + 0]);
            *reinterpret_cast<float4*>(&b[4]) = *reinterpret_cast<const float4*>(&Bs[buf][kk][tx * 8 + 4]);
            #pragma unroll
            for (int i = 0; i < 4; i++)
                #pragma unroll
                for (int j = 0; j < 8; j++)
                    acc[i][j] = fmaf(a[i], b[j], acc[i][j]);
        }
        if (has) {
            As[buf ^ 1][ac + 0][ar] = av_n.x;
            As[buf ^ 1][ac + 1][ar] = av_n.y;
            As[buf ^ 1][ac + 2][ar] = av_n.z;
            As[buf ^ 1][ac + 3][ar] = av_n.w;
            *reinterpret_cast<float2*>(&Bs[buf ^ 1][br][bc]) = bv_n;
            __syncthreads();
            buf ^= 1;
        }
    }

    #pragma unroll
    for (int i = 0; i < 4; i++) {
        const int m = m0 + ty * 4 + i;
        #pragma unroll
        for (int j = 0; j < 8; j++) {
            const int n = tx * 8 + j;
            C[(size_t)m * DE + n] = tanhf(acc[i][j] + bias[n]);
        }
    }
}

// ---------------- BN finalize (512 partials) -----------------
__global__ void bn_finalize_kernel(const float* __restrict__ gamma,
                                   const float* __restrict__ beta)
{
    const int j = threadIdx.x;
    float s = 0.f, q = 0.f;
    #pragma unroll 8
    for (int b = 0; b < 512; b++) { s += g_ps[b * HH + j]; q += g_pq[b * HH + j]; }
    const float mean = s * (1.f / (float)BB);
    const float var  = q * (1.f / (float)BB) - mean * mean;
    const float inv  = rsqrtf(var + 1e-5f);
    const float sc   = gamma[j] * inv;
    g_scale[j] = sc;
    g_shift[j] = beta[j] - mean * sc;
}

// ---------------- codebook squared norms -----------------
__global__ void c2_kernel(const float* __restrict__ cb)
{
    const int k = blockIdx.x * 256 + threadIdx.x;
    if (k < KC) {
        float s = 0.f;
        #pragma unroll
        for (int j = 0; j < DE; j++) {
            float v = cb[(size_t)k * DE + j];
            s = fmaf(v, v, s);
        }
        g_c2[k] = s;
    }
}

// ---------------- codebook -> tf32 hi/lo fragments (fragment order per chunk) ----
__global__ void cvt_cb_kernel(const float* __restrict__ cb)
{
    const int ch = blockIdx.x;
    const int tid = threadIdx.x;
    const float* src = cb + (size_t)ch * 8192;
    #pragma unroll
    for (int t = 0; t < 32; t++) {
        const int lin = t * 256 + tid;
        const int n = lin >> 6, k = lin & 63;
        const float v = src[lin];
        const uint32_t hi = f2tf32(v);
        const uint32_t lo = f2tf32(v - __uint_as_float(hi));
        const int nt = n >> 3, nn = n & 7;
        const int ks = k >> 3, kk = k & 7;
        const int o = ((nt * 8 + ks) * 32 + nn * 4 + (kk & 3)) * 2 + (kk >> 2);
        g_cbhi[ch * 8192 + o] = hi;
        g_cblo[ch * 8192 + o] = lo;
    }
}

// ================= mma.sync tf32 3x-split dist + argmin =================
__device__ __forceinline__ void mma_tf32(float c[4], uint32_t a0, uint32_t a1,
                                         uint32_t a2, uint32_t a3,
                                         uint32_t b0, uint32_t b1) {
    asm volatile(
        "mma.sync.aligned.m16n8k8.row.col.f32.tf32.tf32.f32 "
        "{%0,%1,%2,%3}, {%4,%5,%6,%7}, {%8,%9}, {%0,%1,%2,%3};"
        : "+f"(c[0]), "+f"(c[1]), "+f"(c[2]), "+f"(c[3])
        : "r"(a0), "r"(a1), "r"(a2), "r"(a3), "r"(b0), "r"(b1));
}

#define D_A_HI 0
#define D_A_LO 32768
#define D_B_HI 65536
#define D_B_LO 98304
#define D_C2   131072
#define D_REDF 131584
#define D_REDI 139776
#define D_SMEM 147968

__global__ void __launch_bounds__(256, 1) dist_argmin_mma(
    const float* __restrict__ z, int* __restrict__ idxo)
{
    extern __shared__ char smem[];
    uint32_t* sAhi = (uint32_t*)(smem + D_A_HI);
    uint32_t* sAlo = (uint32_t*)(smem + D_A_LO);
    uint32_t* sBhi = (uint32_t*)(smem + D_B_HI);
    uint32_t* sBlo = (uint32_t*)(smem + D_B_LO);
    float*    c2s  = (float*)(smem + D_C2);
    float*    redF = (float*)(smem + D_REDF);
    int*      redI = (int*)(smem + D_REDI);

    const int tid  = threadIdx.x;
    const int lane = tid & 31;
    const int wid  = tid >> 5;
    const int wr   = wid >> 2;
    const int wc   = wid & 3;
    const int row0 = blockIdx.x * 128;

    // ---- stage Z tile [128 x 64] into fragment-order hi/lo ----
    #pragma unroll
    for (int t = 0; t < 32; t++) {
        const int lin = t * 256 + tid;
        const int r = lin >> 6, k = lin & 63;
        const float v = z[(size_t)(row0 + r) * DE + k];
        const uint32_t hi = f2tf32(v);
        const uint32_t lo = f2tf32(v - __uint_as_float(hi));
        const int mt = r >> 4, rr = r & 15;
        const int ks = k >> 3, kk = k & 7;
        const int fl = (rr & 7) * 4 + (kk & 3);
        const int rg = (rr >> 3) + 2 * (kk >> 2);
        const int o  = ((mt * 8 + ks) * 32 + fl) * 4 + rg;
        sAhi[o] = hi;
        sAlo[o] = lo;
    }

    float bestv[8];
    int   besti[8];
    #pragma unroll
    for (int s = 0; s < 8; s++) { bestv[s] = 3.4e38f; besti[s] = 0; }

    for (int ch = 0; ch < 32; ch++) {
        __syncthreads();
        // ---- stage pre-converted CB chunk fragments (pure copy) ----
        {
            const uint4* gh = (const uint4*)(g_cbhi + ch * 8192);
            const uint4* gl = (const uint4*)(g_cblo + ch * 8192);
            uint4* sh4 = (uint4*)sBhi;
            uint4* sl4 = (uint4*)sBlo;
            #pragma unroll
            for (int t = 0; t < 8; t++) {
                sh4[t * 256 + tid] = gh[t * 256 + tid];
                sl4[t * 256 + tid] = gl[t * 256 + tid];
            }
        }
        if (tid < 128) c2s[tid] = g_c2[ch * 128 + tid];
        __syncthreads();

        // ---- mma mainloop ----
        float acc[4][4][4];
        #pragma unroll
        for (int mt = 0; mt < 4; mt++)
            #pragma unroll
            for (int nt = 0; nt < 4; nt++)
                #pragma unroll
                for (int j = 0; j < 4; j++) acc[mt][nt][j] = 0.f;

        #pragma unroll
        for (int ks = 0; ks < 8; ks++) {
            uint4 ahi[4], alo[4];
            uint2 bhi[4], blo[4];
            #pragma unroll
            for (int mt = 0; mt < 4; mt++) {
                const int o = (((wr * 4 + mt) * 8 + ks) * 32 + lane) * 4;
                ahi[mt] = *reinterpret_cast<const uint4*>(sAhi + o);
                alo[mt] = *reinterpret_cast<const uint4*>(sAlo + o);
            }
            #pragma unroll
            for (int nt = 0; nt < 4; nt++) {
                const int o = (((wc * 4 + nt) * 8 + ks) * 32 + lane) * 2;
                bhi[nt] = *reinterpret_cast<const uint2*>(sBhi + o);
                blo[nt] = *reinterpret_cast<const uint2*>(sBlo + o);
            }
            #pragma unroll
            for (int mt = 0; mt < 4; mt++)
                #pragma unroll
                for (int nt = 0; nt < 4; nt++)
                    mma_tf32(acc[mt][nt], ahi[mt].x, ahi[mt].y, ahi[mt].z, ahi[mt].w,
                             bhi[nt].x, bhi[nt].y);
            #pragma unroll
            for (int mt = 0; mt < 4; mt++)
                #pragma unroll
                for (int nt = 0; nt < 4; nt++)
                    mma_tf32(acc[mt][nt], ahi[mt].x, ahi[mt].y, ahi[mt].z, ahi[mt].w,
                             blo[nt].x, blo[nt].y);
            #pragma unroll
            for (int mt = 0; mt < 4; mt++)
                #pragma unroll
                for (int nt = 0; nt < 4; nt++)
                    mma_tf32(acc[mt][nt], alo[mt].x, alo[mt].y, alo[mt].z, alo[mt].w,
                             bhi[nt].x, bhi[nt].y);
        }

        // ---- epilogue: dist = c2 - 2*dot, per-slot argmin (index increasing) ----
        #pragma unroll
        for (int nt = 0; nt < 4; nt++) {
            const int ncol = wc * 32 + nt * 8 + 2 * (lane & 3);
            const float cc0 = c2s[ncol];
            const float cc1 = c2s[ncol + 1];
            const int gi = ch * 128 + ncol;
            #pragma unroll
            for (int mt = 0; mt < 4; mt++) {
                float d0 = fmaf(-2.f, acc[mt][nt][0], cc0);
                float d1 = fmaf(-2.f, acc[mt][nt][1], cc1);
                float d2 = fmaf(-2.f, acc[mt][nt][2], cc0);
                float d3 = fmaf(-2.f, acc[mt][nt][3], cc1);
                const int s0 = mt * 2, s1 = mt * 2 + 1;
                if (d0 < bestv[s0]) { bestv[s0] = d0; besti[s0] = gi; }
                if (d1 < bestv[s0]) { bestv[s0] = d1; besti[s0] = gi + 1; }
                if (d2 < bestv[s1]) { bestv[s1] = d2; besti[s1] = gi; }
                if (d3 < bestv[s1]) { bestv[s1] = d3; besti[s1] = gi + 1; }
            }
        }
    }

    __syncthreads();
    #pragma unroll
    for (int s = 0; s < 8; s++) {
        const int mt = s >> 1, half = s & 1;
        const int row = wr * 64 + mt * 16 + half * 8 + (lane >> 2);
        const int e = wc * 4 + (lane & 3);
        redF[row * 16 + e] = bestv[s];
        redI[row * 16 + e] = besti[s];
    }
    __syncthreads();
    if (tid < 128) {
        float bs = 3.4e38f;
        int   b  = 0x7fffffff;
        #pragma unroll
        for (int e = 0; e < 16; e++) {
            const float sv = redF[tid * 16 + e];
            const int   iv = redI[tid * 16 + e];
            if (sv < bs || (sv == bs && iv < b)) { bs = sv; b = iv; }
        }
        idxo[row0 + tid] = b;
    }
}

// ---------------- output writer ----------------
__global__ void writeout_kernel(const float* __restrict__ cb,
                                float* __restrict__ outf, int* __restrict__ outi,
                                int mode)
{
    const int gid = blockIdx.x * 256 + threadIdx.x;
    const int row = gid >> 6, j = gid & 63;
    const int id = g_idx[row];
    if (mode == 0) {
        if (j == 0) outf[row] = (float)id;
        outf[BB + gid] = cb[(size_t)id * DE + j];
    } else if (mode == 1) {
        outf[gid] = cb[(size_t)id * DE + j];
    } else {
        if (j == 0) outi[row] = id;
    }
}

// ---------------- launch -----------------------------------------------------------
extern "C" void kernel_launch(void* const* d_in, const int* in_sizes, int n_in,
                              void* d_out, int out_size)
{
    const float* x     = (const float*)d_in[0];
    const float* W1    = (const float*)d_in[1];
    const float* b1    = (const float*)d_in[2];
    const float* gamma = (const float*)d_in[3];
    const float* beta  = (const float*)d_in[4];
    const float* W2    = (const float*)d_in[5];
    const float* b2    = (const float*)d_in[6];
    const float* W3    = (const float*)d_in[7];
    const float* b3    = (const float*)d_in[8];
    const float* cb    = (const float*)d_in[9];

    float *h1p = nullptr, *h2p = nullptr, *zp = nullptr, *psp = nullptr, *pqp = nullptr;
    int *idxp = nullptr;
    cudaGetSymbolAddress((void**)&h1p, g_h1);
    cudaGetSymbolAddress((void**)&h2p, g_h2);
    cudaGetSymbolAddress((void**)&zp,  g_z);
    cudaGetSymbolAddress((void**)&psp, g_ps);
    cudaGetSymbolAddress((void**)&pqp, g_pq);
    cudaGetSymbolAddress((void**)&idxp, g_idx);

    cudaFuncSetAttribute(dist_argmin_mma, cudaFuncAttributeMaxDynamicSharedMemorySize, D_SMEM);

    dim3 blk(256);

    // codebook prep (independent of encoder chain)
    c2_kernel<<<KC / 256, 256>>>(cb);
    cvt_cb_kernel<<<32, 256>>>(cb);

    // h1 = x @ W1 + b1, fused BN partial sums
    sgemm128_kernel<0, false, true><<<dim3(HH / 128, BB / 128), blk>>>(
        x, W1, b1, h1p, psp, pqp, BB, HH, DIN);

    bn_finalize_kernel<<<1, HH>>>(gamma, beta);

    // h2 = relu( bnrelu(h1) @ W2 + b2 )
    sgemm128_kernel<1, true, false><<<dim3(HH / 128, BB / 128), blk>>>(
        h1p, W2, b2, h2p, nullptr, nullptr, BB, HH, HH);

    // z = tanh( h2 @ W3 + b3 )
    sgemm_z_kernel<<<BB / 128, blk>>>(h2p, W3, b3, zp, HH);

    // tensor-core dist/argmin
    dist_argmin_mma<<<BB / 128, 256, D_SMEM>>>(zp, idxp);

    // outputs
    int mode;
    if      (out_size == BB * (DE + 1)) mode = 0;
    else if (out_size == BB * DE)       mode = 1;
    else                                mode = 2;
    writeout_kernel<<<(BB * DE) / 256, 256>>>(cb, (float*)d_out, (int*)d_out, mode);
}